// round 8
// baseline (speedup 1.0000x reference)
#include <cuda_runtime.h>

#define BB   32
#define LL   4096
#define IN   1024
#define QSZ  64
#define VSZ  256
#define HH   16
#define NCHUNK 16          // k_att blocks per batch (l-chunks of 256)
#define LCH  256
#define NSLOT 64           // partial slots = NCHUNK * 4 (l-quarters)

// Scratch (__device__ globals; no allocation allowed)
__device__ float g_q[BB*IN];                     // 128 KB
__device__ float g_partial[BB*NSLOT*HH*VSZ];     // 33.5 MB
__device__ float g_s[BB*NSLOT*HH];               // per-slot expsum
__device__ float g_pv[BB*HH*VSZ];                // 512 KB
__device__ float g_dummy[32];

typedef unsigned long long u64;

__device__ __forceinline__ u64 pack2(float lo, float hi) {
    u64 r; asm("mov.b64 %0, {%1, %2};" : "=l"(r) : "f"(lo), "f"(hi)); return r;
}
__device__ __forceinline__ u64 fma2(u64 a, u64 b, u64 c) {
    u64 d; asm("fma.rn.f32x2 %0, %1, %2, %3;" : "=l"(d) : "l"(a), "l"(b), "l"(c)); return d;
}
__device__ __forceinline__ float2 unpack2(u64 v) {
    float2 f; asm("mov.b64 {%0, %1}, %2;" : "=f"(f.x), "=f"(f.y) : "l"(v)); return f;
}

// Dummy: keeps k_att as the 4th launch for the harness ncu capture.
__global__ void k_dummy() { if (threadIdx.x == 0) g_dummy[blockIdx.x] = 1.0f; }

// ============================================================
// K1: q[b,n] = query[b,:].Wq[n,:] + bq[n]
// ============================================================
__global__ void __launch_bounds__(256) k_q(const float* __restrict__ query,
                                           const float* __restrict__ Wq,
                                           const float* __restrict__ bq) {
    __shared__ float qsm[8 * IN];
    int tid = threadIdx.x, lane = tid & 31, warp = tid >> 5;
    int n  = blockIdx.x * 8 + warp;
    int b0 = blockIdx.y * 8;

    const float4* qg = (const float4*)(query + (size_t)b0 * IN);
    float4* qs4 = (float4*)qsm;
    for (int i = tid; i < 8 * IN / 4; i += 256) qs4[i] = __ldg(qg + i);
    __syncthreads();

    const float4* w4 = (const float4*)(Wq + (size_t)n * IN);
    float acc[8];
#pragma unroll
    for (int b = 0; b < 8; b++) acc[b] = 0.f;

#pragma unroll
    for (int it = 0; it < 8; it++) {
        int idx = it * 32 + lane;
        float4 w = __ldg(w4 + idx);
#pragma unroll
        for (int b = 0; b < 8; b++) {
            float4 q = qs4[b * (IN / 4) + idx];
            acc[b] += w.x * q.x + w.y * q.y + w.z * q.z + w.w * q.w;
        }
    }
#pragma unroll
    for (int b = 0; b < 8; b++) {
#pragma unroll
        for (int o = 16; o; o >>= 1) acc[b] += __shfl_xor_sync(0xffffffffu, acc[b], o);
    }
    if (lane == 0) {
        float bias = bq[n];
#pragma unroll
        for (int b = 0; b < 8; b++)
            g_q[(size_t)(b0 + b) * IN + n] = acc[b] + bias;
    }
}

// ============================================================
// K2: fused scores + exp + weighted value partial sum. 512 threads.
// Phase A: thread = (l = tid>>1, dhalf = tid&1). Each thread dots half
//   of QSZ for all 16 h (acc = 16 u64), shfl_xor(1) completes the sums,
//   both lane-partners compute exp, each writes 4 h-pair slots.
// ps layout: [l][8 slots of 16B], slot(l,hp) = (hp+l)&7 = {e(2hp)dup, e(2hp+1)dup}.
// Phase B: thread = (d4 = t&63, hg = (t>>6)&1, lq = t>>7). 64 l, 8 h,
//   1 float4 d-col. Per l: 1 LDG.128 + 4 LDS.128 (broadcast) + 16 FFMA2.
//   acc = 16 regs. Slot out = c*4 + lq.
// ============================================================
__global__ void __launch_bounds__(512, 2) k_att(const float* __restrict__ key,
                                                const float* __restrict__ value) {
    __shared__ u64  qs[HH * QSZ / 2];          // 4 KB
    __shared__ ulonglong2 ps[LCH][8];          // 32 KB
    __shared__ float wsum[512];                // 2 KB

    int b = blockIdx.y, c = blockIdx.x;
    int tid = threadIdx.x;

    const float2* qsrc = (const float2*)(g_q + (size_t)b * IN);
    for (int i = tid; i < HH * QSZ / 2; i += 512) {
        float2 v = qsrc[i];
        qs[i] = pack2(v.x, v.y);
    }
    __syncthreads();

    // ---- Phase A ----
    {
        int l = tid >> 1, dh = tid & 1;
        const float4* k4 = (const float4*)(key + ((size_t)b * LL + (size_t)c * LCH + l) * QSZ) + dh * 8;

        u64 acc[HH];
#pragma unroll
        for (int h = 0; h < HH; h++) acc[h] = pack2(0.f, 0.f);

#pragma unroll
        for (int i = 0; i < 8; i++) {
            float4 kk = __ldg(k4 + i);
            u64 ka = pack2(kk.x, kk.y);
            u64 kb = pack2(kk.z, kk.w);
            int d4 = dh * 8 + i;
#pragma unroll
            for (int h = 0; h < HH; h++) {
                acc[h] = fma2(ka, qs[h * 32 + 2 * d4],     acc[h]);
                acc[h] = fma2(kb, qs[h * 32 + 2 * d4 + 1], acc[h]);
            }
        }
        float e[HH];
#pragma unroll
        for (int h = 0; h < HH; h++) {
            float2 f = unpack2(acc[h]);
            float s = f.x + f.y;
            s += __shfl_xor_sync(0xffffffffu, s, 1);
            e[h] = __expf(s * 0.125f);
        }
#pragma unroll
        for (int j = 0; j < 4; j++) {
            int hp = dh * 4 + j;
            int slot = (hp + l) & 7;
            ulonglong2 w;
            w.x = pack2(e[2 * hp],     e[2 * hp]);
            w.y = pack2(e[2 * hp + 1], e[2 * hp + 1]);
            ps[l][slot] = w;
        }
    }
    __syncthreads();

    // ---- per-(h, l-quarter) expsum from smem ----
    {
        int h = tid & 15, q = (tid >> 4) & 3, chunk = tid >> 6;   // chunk 0..7
        int hp = h >> 1, sub = h & 1;
        float s = 0.f;
#pragma unroll
        for (int i = 0; i < 8; i++) {
            int l = q * 64 + chunk * 8 + i;
            const u64* row = (const u64*)&ps[l][0];
            int slot = (hp + l) & 7;
            float2 f = unpack2(row[slot * 2 + sub]);
            s += f.x;
        }
        wsum[tid] = s;
    }
    __syncthreads();
    if (tid < 64) {
        int h = tid & 15, q = tid >> 4;
        float S = 0.f;
#pragma unroll
        for (int chunk = 0; chunk < 8; chunk++)
            S += wsum[chunk * 64 + q * 16 + h];
        g_s[((size_t)b * NSLOT + (size_t)c * 4 + q) * HH + h] = S;
    }

    // ---- Phase B ----
    int d4 = tid & 63, hg = (tid >> 6) & 1, lq = tid >> 7;        // lq 0..3
    const float4* vb = (const float4*)(value +
        ((size_t)b * LL + (size_t)c * LCH + (size_t)lq * 64) * VSZ) + d4;

    u64 accA[8], accB[8];
#pragma unroll
    for (int j = 0; j < 8; j++) { accA[j] = pack2(0.f, 0.f); accB[j] = pack2(0.f, 0.f); }

#pragma unroll 4
    for (int i = 0; i < 64; i++) {
        int l = lq * 64 + i;
        float4 vv = __ldg(vb + (size_t)i * (VSZ / 4));
        u64 v01 = pack2(vv.x, vv.y);
        u64 v23 = pack2(vv.z, vv.w);
#pragma unroll
        for (int j = 0; j < 4; j++) {
            int hp = hg * 4 + j;
            int slot = (hp + l) & 7;
            ulonglong2 pp = ps[l][slot];       // LDS.128 broadcast
            accA[2 * j]     = fma2(v01, pp.x, accA[2 * j]);
            accB[2 * j]     = fma2(v23, pp.x, accB[2 * j]);
            accA[2 * j + 1] = fma2(v01, pp.y, accA[2 * j + 1]);
            accB[2 * j + 1] = fma2(v23, pp.y, accB[2 * j + 1]);
        }
    }

    int slot_out = c * 4 + lq;
    float* base = g_partial + ((size_t)(b * NSLOT + slot_out) * HH + hg * 8) * VSZ + d4 * 4;
#pragma unroll
    for (int j = 0; j < 8; j++) {
        float2 a = unpack2(accA[j]);
        float2 bb = unpack2(accB[j]);
        *(float4*)(base + (size_t)j * VSZ) = make_float4(a.x, a.y, bb.x, bb.y);
    }
}

// ============================================================
// K3: combine 64 slots: sum partials, sum S, normalize.
// ============================================================
__global__ void __launch_bounds__(256) k_red() {
    int g = blockIdx.x * 256 + threadIdx.x;
    int d2 = g & 127;
    int h  = (g >> 7) & (HH - 1);
    int b  = g >> 11;

    const float* sp = g_s + (size_t)b * NSLOT * HH + h;
    float S = 0.f;
#pragma unroll 8
    for (int c = 0; c < NSLOT; c++) S += sp[c * HH];

    const float2* pp = (const float2*)(g_partial + ((size_t)b * NSLOT * HH + h) * VSZ) + d2;
    float2 pv = make_float2(0.f, 0.f);
#pragma unroll 8
    for (int c = 0; c < NSLOT; c++) {
        float2 v = pp[(size_t)c * HH * (VSZ / 2)];
        pv.x += v.x;
        pv.y += v.y;
    }
    float inv = 1.0f / S;
    ((float2*)(g_pv + (size_t)(b * HH + h) * VSZ))[d2] = make_float2(pv.x * inv, pv.y * inv);
}

// ============================================================
// K4: out[b,n] = Wv[n,:].pv[b, n>>6, :] + bv[n]
// ============================================================
__global__ void __launch_bounds__(256) k_out(const float* __restrict__ Wv,
                                             const float* __restrict__ bv,
                                             float* __restrict__ out) {
    __shared__ float pvs[8 * VSZ];
    int tid = threadIdx.x, lane = tid & 31, warp = tid >> 5;
    int n  = blockIdx.x * 8 + warp;
    int b0 = blockIdx.y * 8;
    int h  = (blockIdx.x * 8) >> 6;

    float4* pv4 = (float4*)pvs;
    for (int i = tid; i < 8 * VSZ / 4; i += 256) {
        int bl = i / (VSZ / 4), k4 = i % (VSZ / 4);
        pv4[i] = ((const float4*)(g_pv + (size_t)((b0 + bl) * HH + h) * VSZ))[k4];
    }
    __syncthreads();

    const float4* w4 = (const float4*)(Wv + (size_t)n * VSZ);
    float acc[8];
#pragma unroll
    for (int b = 0; b < 8; b++) acc[b] = 0.f;

#pragma unroll
    for (int it = 0; it < 2; it++) {
        int idx = it * 32 + lane;
        float4 w = __ldg(w4 + idx);
#pragma unroll
        for (int b = 0; b < 8; b++) {
            float4 p = pv4[b * (VSZ / 4) + idx];
            acc[b] += w.x * p.x + w.y * p.y + w.z * p.z + w.w * p.w;
        }
    }
#pragma unroll
    for (int b = 0; b < 8; b++) {
#pragma unroll
        for (int o = 16; o; o >>= 1) acc[b] += __shfl_xor_sync(0xffffffffu, acc[b], o);
    }
    if (lane == 0) {
        float bias = bv[n];
#pragma unroll
        for (int b = 0; b < 8; b++)
            out[(size_t)(b0 + b) * IN + n] = acc[b] + bias;
    }
}

// ============================================================
extern "C" void kernel_launch(void* const* d_in, const int* in_sizes, int n_in,
                              void* d_out, int out_size) {
    const float* query = (const float*)d_in[0];
    const float* key   = (const float*)d_in[1];
    const float* value = (const float*)d_in[2];
    const float* Wq    = (const float*)d_in[3];
    const float* bq    = (const float*)d_in[4];
    const float* Wv    = (const float*)d_in[5];
    const float* bv    = (const float*)d_in[6];
    float* out = (float*)d_out;

    k_q<<<dim3(IN / 8, BB / 8), 256>>>(query, Wq, bq);
    k_dummy<<<1, 32>>>();                       // shift profile slot
    k_dummy<<<1, 32>>>();                       // -> k_att is 4th launch
    k_att<<<dim3(NCHUNK, BB), 512>>>(key, value);
    k_red<<<BB * HH * (VSZ / 2) / 256, 256>>>();
    k_out<<<dim3(IN / 8, BB / 8), 256>>>(Wv, bv, out);
}

// round 9
// speedup vs baseline: 1.6675x; 1.6675x over previous
#include <cuda_runtime.h>

#define BB   32
#define LL   4096
#define IN   1024
#define QSZ  64
#define VSZ  256
#define HH   16
#define NCHUNK 16          // k_att blocks per batch (l-chunks of 256)
#define LCH  256
#define NSLOT 16           // one partial slot per chunk

// Scratch (__device__ globals; no allocation allowed)
__device__ float g_q[BB*IN];                     // 128 KB
__device__ float g_partial[BB*NSLOT*HH*VSZ];     // 8 MB
__device__ float g_s[BB*NSLOT*HH];               // per-slot expsum
__device__ float g_pv[BB*HH*VSZ];                // 512 KB
__device__ float g_dummy[32];

// ---- tf32 mma helpers ----
__device__ __forceinline__ unsigned f2tf(float f) {
    unsigned u; asm("cvt.rna.tf32.f32 %0, %1;" : "=r"(u) : "f"(f)); return u;
}
__device__ __forceinline__ void mma_tf32(float& c0, float& c1, float& c2, float& c3,
                                         unsigned a0, unsigned a1, unsigned a2, unsigned a3,
                                         unsigned b0, unsigned b1) {
    asm("mma.sync.aligned.m16n8k8.row.col.f32.tf32.tf32.f32 "
        "{%0,%1,%2,%3}, {%4,%5,%6,%7}, {%8,%9}, {%0,%1,%2,%3};"
        : "+f"(c0), "+f"(c1), "+f"(c2), "+f"(c3)
        : "r"(a0), "r"(a1), "r"(a2), "r"(a3), "r"(b0), "r"(b1));
}

// Dummy: keeps k_att as the 4th launch for the harness ncu capture.
__global__ void k_dummy() { if (threadIdx.x == 0) g_dummy[blockIdx.x] = 1.0f; }

// ============================================================
// K1: q[b,n] = query[b,:].Wq[n,:] + bq[n]
// ============================================================
__global__ void __launch_bounds__(256) k_q(const float* __restrict__ query,
                                           const float* __restrict__ Wq,
                                           const float* __restrict__ bq) {
    __shared__ float qsm[8 * IN];
    int tid = threadIdx.x, lane = tid & 31, warp = tid >> 5;
    int n  = blockIdx.x * 8 + warp;
    int b0 = blockIdx.y * 8;

    const float4* qg = (const float4*)(query + (size_t)b0 * IN);
    float4* qs4 = (float4*)qsm;
    for (int i = tid; i < 8 * IN / 4; i += 256) qs4[i] = __ldg(qg + i);
    __syncthreads();

    const float4* w4 = (const float4*)(Wq + (size_t)n * IN);
    float acc[8];
#pragma unroll
    for (int b = 0; b < 8; b++) acc[b] = 0.f;

#pragma unroll
    for (int it = 0; it < 8; it++) {
        int idx = it * 32 + lane;
        float4 w = __ldg(w4 + idx);
#pragma unroll
        for (int b = 0; b < 8; b++) {
            float4 q = qs4[b * (IN / 4) + idx];
            acc[b] += w.x * q.x + w.y * q.y + w.z * q.z + w.w * q.w;
        }
    }
#pragma unroll
    for (int b = 0; b < 8; b++) {
#pragma unroll
        for (int o = 16; o; o >>= 1) acc[b] += __shfl_xor_sync(0xffffffffu, acc[b], o);
    }
    if (lane == 0) {
        float bias = bq[n];
#pragma unroll
        for (int b = 0; b < 8; b++)
            g_q[(size_t)(b0 + b) * IN + n] = acc[b] + bias;
    }
}

// ============================================================
// K2: fused scores + exp + weighted value sum, tf32 tensor cores.
// Block (c, b): 256 threads = 8 warps; l-chunk of 256, all 16 h, all 256 d.
//
// Phase A (scores = q[16,64] @ key^T): warp w owns l-tile [w*32, w*32+32).
//   Per k-chunk (8): A-frags from qs smem, B-frags from gmem key
//   (full-sector coalesced), 4 HMMA. C-frags -> exp -> ps (tf32 bits).
// Phase B (pv = p[16,256l] @ v[256l, 256d]): warp w owns d-tile [w*32, ..+32).
//   Per l-chunk (8): 4 LDS (A-frags, conflict-free stride-24) +
//   8 LDG.32 (v, full sectors, read exactly once) + 4 HMMA.
// ============================================================
#define QS_STRIDE 68
#define PS_STRIDE 24

__global__ void __launch_bounds__(256) k_att(const float* __restrict__ key,
                                             const float* __restrict__ value) {
    __shared__ unsigned qs[HH * QS_STRIDE];    // q as tf32 bits, ~4.4 KB
    __shared__ unsigned ps[LCH * PS_STRIDE];   // exp weights tf32 bits, 24 KB
    __shared__ float wsum[8 * HH];

    int b = blockIdx.y, c = blockIdx.x;
    int tid = threadIdx.x, lane = tid & 31, w = tid >> 5;
    int qr = lane >> 2, qc = lane & 3;         // lane/4, lane%4

    // stage q[16][64] as tf32
    for (int i = tid; i < HH * QSZ; i += 256) {
        int h = i >> 6, d = i & 63;
        qs[h * QS_STRIDE + d] = f2tf(g_q[(size_t)b * IN + i]);
    }
    __syncthreads();

    // ---- Phase A ----
    {
        int l0w = w * 32;
        const float* kb = key + ((size_t)b * LL + (size_t)c * LCH) * QSZ;
        float acc[4][4];
#pragma unroll
        for (int t = 0; t < 4; t++)
#pragma unroll
            for (int j = 0; j < 4; j++) acc[t][j] = 0.f;

#pragma unroll
        for (int k0 = 0; k0 < QSZ; k0 += 8) {
            unsigned a0 = qs[qr * QS_STRIDE + k0 + qc];
            unsigned a1 = qs[(qr + 8) * QS_STRIDE + k0 + qc];
            unsigned a2 = qs[qr * QS_STRIDE + k0 + qc + 4];
            unsigned a3 = qs[(qr + 8) * QS_STRIDE + k0 + qc + 4];
#pragma unroll
            for (int t = 0; t < 4; t++) {
                int l = l0w + t * 8 + qr;
                unsigned b0 = f2tf(__ldg(kb + (size_t)l * QSZ + k0 + qc));
                unsigned b1 = f2tf(__ldg(kb + (size_t)l * QSZ + k0 + qc + 4));
                mma_tf32(acc[t][0], acc[t][1], acc[t][2], acc[t][3],
                         a0, a1, a2, a3, b0, b1);
            }
        }

        float slo = 0.f, shi = 0.f;
#pragma unroll
        for (int t = 0; t < 4; t++) {
            int lb = l0w + t * 8 + 2 * qc;
            float e0 = __expf(acc[t][0] * 0.125f);
            float e1 = __expf(acc[t][1] * 0.125f);
            float e2 = __expf(acc[t][2] * 0.125f);
            float e3 = __expf(acc[t][3] * 0.125f);
            slo += e0 + e1;
            shi += e2 + e3;
            ps[lb * PS_STRIDE + qr]           = f2tf(e0);
            ps[(lb + 1) * PS_STRIDE + qr]     = f2tf(e1);
            ps[lb * PS_STRIDE + qr + 8]       = f2tf(e2);
            ps[(lb + 1) * PS_STRIDE + qr + 8] = f2tf(e3);
        }
        slo += __shfl_xor_sync(0xffffffffu, slo, 1);
        slo += __shfl_xor_sync(0xffffffffu, slo, 2);
        shi += __shfl_xor_sync(0xffffffffu, shi, 1);
        shi += __shfl_xor_sync(0xffffffffu, shi, 2);
        if (qc == 0) {
            wsum[w * HH + qr]     = slo;
            wsum[w * HH + qr + 8] = shi;
        }
    }
    __syncthreads();
    if (tid < HH) {
        float S = 0.f;
#pragma unroll
        for (int i = 0; i < 8; i++) S += wsum[i * HH + tid];
        g_s[((size_t)b * NSLOT + c) * HH + tid] = S;
    }

    // ---- Phase B ----
    {
        int d0w = w * 32;
        const float* vb = value + ((size_t)b * LL + (size_t)c * LCH) * VSZ;
        float acc[4][4];
#pragma unroll
        for (int t = 0; t < 4; t++)
#pragma unroll
            for (int j = 0; j < 4; j++) acc[t][j] = 0.f;

#pragma unroll 4
        for (int chunk = 0; chunk < 32; chunk++) {
            int l0 = chunk * 8;
            unsigned a0 = ps[(l0 + qc) * PS_STRIDE + qr];
            unsigned a1 = ps[(l0 + qc) * PS_STRIDE + qr + 8];
            unsigned a2 = ps[(l0 + qc + 4) * PS_STRIDE + qr];
            unsigned a3 = ps[(l0 + qc + 4) * PS_STRIDE + qr + 8];
#pragma unroll
            for (int t = 0; t < 4; t++) {
                int d0 = d0w + t * 8;
                unsigned b0 = f2tf(__ldg(vb + (size_t)(l0 + qc) * VSZ + d0 + qr));
                unsigned b1 = f2tf(__ldg(vb + (size_t)(l0 + qc + 4) * VSZ + d0 + qr));
                mma_tf32(acc[t][0], acc[t][1], acc[t][2], acc[t][3],
                         a0, a1, a2, a3, b0, b1);
            }
        }

        float* outp = g_partial + ((size_t)(b * NSLOT + c) * HH) * VSZ;
#pragma unroll
        for (int t = 0; t < 4; t++) {
            int d = d0w + t * 8 + 2 * qc;
            *(float2*)(outp + (size_t)qr * VSZ + d)       = make_float2(acc[t][0], acc[t][1]);
            *(float2*)(outp + (size_t)(qr + 8) * VSZ + d) = make_float2(acc[t][2], acc[t][3]);
        }
    }
}

// ============================================================
// K3: combine 16 slots: sum partials, sum S, normalize.
// ============================================================
__global__ void __launch_bounds__(256) k_red() {
    int g = blockIdx.x * 256 + threadIdx.x;
    int d2 = g & 127;
    int h  = (g >> 7) & (HH - 1);
    int b  = g >> 11;

    const float* sp = g_s + (size_t)b * NSLOT * HH + h;
    float S = 0.f;
#pragma unroll
    for (int c = 0; c < NSLOT; c++) S += sp[c * HH];

    const float2* pp = (const float2*)(g_partial + ((size_t)b * NSLOT * HH + h) * VSZ) + d2;
    float2 pv = make_float2(0.f, 0.f);
#pragma unroll
    for (int c = 0; c < NSLOT; c++) {
        float2 v = pp[(size_t)c * HH * (VSZ / 2)];
        pv.x += v.x;
        pv.y += v.y;
    }
    float inv = 1.0f / S;
    ((float2*)(g_pv + (size_t)(b * HH + h) * VSZ))[d2] = make_float2(pv.x * inv, pv.y * inv);
}

// ============================================================
// K4: out[b,n] = Wv[n,:].pv[b, n>>6, :] + bv[n]
// ============================================================
__global__ void __launch_bounds__(256) k_out(const float* __restrict__ Wv,
                                             const float* __restrict__ bv,
                                             float* __restrict__ out) {
    __shared__ float pvs[8 * VSZ];
    int tid = threadIdx.x, lane = tid & 31, warp = tid >> 5;
    int n  = blockIdx.x * 8 + warp;
    int b0 = blockIdx.y * 8;
    int h  = (blockIdx.x * 8) >> 6;

    float4* pv4 = (float4*)pvs;
    for (int i = tid; i < 8 * VSZ / 4; i += 256) {
        int bl = i / (VSZ / 4), k4 = i % (VSZ / 4);
        pv4[i] = ((const float4*)(g_pv + (size_t)((b0 + bl) * HH + h) * VSZ))[k4];
    }
    __syncthreads();

    const float4* w4 = (const float4*)(Wv + (size_t)n * VSZ);
    float acc[8];
#pragma unroll
    for (int b = 0; b < 8; b++) acc[b] = 0.f;

#pragma unroll
    for (int it = 0; it < 2; it++) {
        int idx = it * 32 + lane;
        float4 w = __ldg(w4 + idx);
#pragma unroll
        for (int b = 0; b < 8; b++) {
            float4 p = pv4[b * (VSZ / 4) + idx];
            acc[b] += w.x * p.x + w.y * p.y + w.z * p.z + w.w * p.w;
        }
    }
#pragma unroll
    for (int b = 0; b < 8; b++) {
#pragma unroll
        for (int o = 16; o; o >>= 1) acc[b] += __shfl_xor_sync(0xffffffffu, acc[b], o);
    }
    if (lane == 0) {
        float bias = bv[n];
#pragma unroll
        for (int b = 0; b < 8; b++)
            out[(size_t)(b0 + b) * IN + n] = acc[b] + bias;
    }
}

// ============================================================
extern "C" void kernel_launch(void* const* d_in, const int* in_sizes, int n_in,
                              void* d_out, int out_size) {
    const float* query = (const float*)d_in[0];
    const float* key   = (const float*)d_in[1];
    const float* value = (const float*)d_in[2];
    const float* Wq    = (const float*)d_in[3];
    const float* bq    = (const float*)d_in[4];
    const float* Wv    = (const float*)d_in[5];
    const float* bv    = (const float*)d_in[6];
    float* out = (float*)d_out;

    k_q<<<dim3(IN / 8, BB / 8), 256>>>(query, Wq, bq);
    k_dummy<<<1, 32>>>();                       // shift profile slot
    k_dummy<<<1, 32>>>();                       // -> k_att is 4th launch
    k_att<<<dim3(NCHUNK, BB), 256>>>(key, value);
    k_red<<<BB * HH * (VSZ / 2) / 256, 256>>>();
    k_out<<<dim3(IN / 8, BB / 8), 256>>>(Wv, bv, out);
}